// round 10
// baseline (speedup 1.0000x reference)
#include <cuda_runtime.h>
#include <cuda_bf16.h>
#include <cstdint>
#include <math.h>

#define BTOT 32768
#define KC 64
#define DD 64
#define LOG_2PI 1.8378770664093453f

// ---- persistent scratch ----
__device__ __nv_bfloat16 g_LinvBF[KC][DD * DD];  // [k][i*64+j] (lower-tri, upper=0)
__device__ float    g_Cvec[KC][DD];              // c_k[i] = (Linv mu)[i], fp32
__device__ float    g_const2[KC];  // logw - hld - 0.5*D*log2pi
__device__ double   g_partial[512];
__device__ unsigned g_cnt;

// ============================================================
// Kernel A: preprocess, 64 blocks x 256 threads (8 warps).
// Warp-register column solver.
// ============================================================
__global__ __launch_bounds__(256) void prep_kernel(const float* __restrict__ means_raw,
                                                   const float* __restrict__ scale_raw,
                                                   const float* __restrict__ weights_raw) {
    const int k = blockIdx.x;
    const int t = threadIdx.x;
    const int w = t >> 5, l = t & 31;
    __shared__ float Lp[DD][DD + 1];   // strictly-lower of L (else 0)
    __shared__ float R[DD][DD + 1];    // Linv (row-major), upper = 0
    __shared__ float dg[DD];           // raw diag
    __shared__ float aux[DD];
    __shared__ float aux2[DD];
    __shared__ float mv[DD];
    const float g2 = 1.0f / 512.0f;
    const float g1 = 1.0f / 64.0f;

    if (k == 0 && t == 0) g_cnt = 0;

    for (int idx = t; idx < DD * DD; idx += 256) {
        int i = idx >> 6, j = idx & 63;
        float raw = scale_raw[k * DD * DD + idx] * g2;
        Lp[i][j] = (i > j) ? raw : 0.0f;
        if (i == j) dg[i] = raw;
    }
    float v = 0.0f;
    if (t < 64) {
        mv[t] = means_raw[k * DD + t] * g1;
        v = weights_raw[t] * 0.125f;
        aux[t] = v;
    }
    __syncthreads();

    for (int s = 32; s > 0; s >>= 1) {
        if (t < s) aux[t] = fmaxf(aux[t], aux[t + s]);
        __syncthreads();
    }
    float m = aux[0];
    __syncthreads();
    if (t < 64) { aux2[t] = expf(v - m); aux[t] = dg[t]; }
    __syncthreads();
    for (int s = 32; s > 0; s >>= 1) {
        if (t < s) { aux2[t] += aux2[t + s]; aux[t] += aux[t + s]; }
        __syncthreads();
    }
    float lse = m + logf(aux2[0]);
    float hld = aux[0];

    // register column solver: lane l = rows l, l+32
    float rd0 = __expf(-dg[l]);
    float rd1 = __expf(-dg[l + 32]);
    float p0[8], p1[8], y0[8], y1[8];
#pragma unroll
    for (int j = 0; j < 8; j++) { p0[j] = p1[j] = y0[j] = y1[j] = 0.0f; }
    const int cbase = w * 8;

    for (int i = 0; i < DD; i++) {
        float Llo = Lp[l][i];
        float Lhi = Lp[l + 32][i];
        const int own = i & 31;
        const int half = i >> 5;
        float rdo = half ? rd1 : rd0;
#pragma unroll
        for (int j = 0; j < 8; j++) {
            const int c = cbase + j;
            float pown = half ? p1[j] : p0[j];
            float cv = ((i == c) ? 1.0f : 0.0f) - pown;
            cv *= rdo;
            float yb = __shfl_sync(0xffffffffu, cv, own);
            yb = (i >= c) ? yb : 0.0f;
            if (l == own) { if (half) y1[j] = yb; else y0[j] = yb; }
            p0[j] = fmaf(Llo, yb, p0[j]);
            p1[j] = fmaf(Lhi, yb, p1[j]);
        }
    }

#pragma unroll
    for (int j = 0; j < 8; j++) {
        R[l][cbase + j]      = y0[j];
        R[l + 32][cbase + j] = y1[j];
    }
    __syncthreads();

    if (t < 64) {
        float c = 0.0f;
        for (int j = 0; j <= t; j++) c += R[t][j] * mv[j];
        g_Cvec[k][t] = c;
    }

    for (int idx = t; idx < DD * DD; idx += 256) {
        int i = idx >> 6, j = idx & 63;
        g_LinvBF[k][idx] = __float2bfloat16(R[i][j]);
    }

    if (t == 0) {
        float vk = weights_raw[k] * 0.125f;
        g_const2[k] = (vk - lse) - hld - 0.5f * 64.0f * LOG_2PI;
    }
}

// ============================================================
// Main kernel: bf16 HMMA, 512 CTAs x 128 thr (4 warps, warp tile
// M16xN64, CTA tile 64 rows). ~46KB smem -> 4 CTAs/SM, all 512
// CTAs resident in ONE wave (~14 warps/SM). 4-slot ring, groups
// of 2 comps per barrier pair. acc init to -c_k, triangular skip.
// ============================================================
#define ROWB 144                        // 72 bf16 per smem row
#define XS_BYTES (64 * ROWB)            // 9216
#define LB_OFF   XS_BYTES
#define LB_BYTES (64 * ROWB)            // 9216 per slot
#define NSLOT 4
#define CV_OFF   (LB_OFF + NSLOT * LB_BYTES)    // 46080
#define CV_BYTES (NSLOT * 256)                  // 1024
#define DSM_OFF  (CV_OFF + CV_BYTES)            // 47104
#define SMEM_TOTAL (DSM_OFF + 4 * 8)            // 47136

__device__ __forceinline__ void ldmx4(uint32_t a[4], uint32_t addr) {
    asm volatile("ldmatrix.sync.aligned.m8n8.x4.shared.b16 {%0,%1,%2,%3}, [%4];"
                 : "=r"(a[0]), "=r"(a[1]), "=r"(a[2]), "=r"(a[3]) : "r"(addr));
}
__device__ __forceinline__ void mma16816(float d[4], const uint32_t a[4],
                                         uint32_t b0, uint32_t b1) {
    asm volatile(
        "mma.sync.aligned.m16n8k16.row.col.f32.bf16.bf16.f32 "
        "{%0,%1,%2,%3}, {%4,%5,%6,%7}, {%8,%9}, {%0,%1,%2,%3};"
        : "+f"(d[0]), "+f"(d[1]), "+f"(d[2]), "+f"(d[3])
        : "r"(a[0]), "r"(a[1]), "r"(a[2]), "r"(a[3]), "r"(b0), "r"(b1));
}
// stage Linv[comp] into slot + its c vector (256B)
__device__ __forceinline__ void cp_slot(uint32_t LbA, uint32_t CvA, int slot,
                                        int comp, int t) {
    uint32_t dstB = LbA + slot * LB_BYTES;
    const __nv_bfloat16* src = g_LinvBF[comp];
#pragma unroll
    for (int q = 0; q < 4; q++) {
        int f = t + q * 128;            // 0..511 16B chunks
        uint32_t dst = dstB + (f >> 3) * ROWB + (f & 7) * 16;
        asm volatile("cp.async.ca.shared.global [%0], [%1], 16;"
                     :: "r"(dst), "l"(src + f * 8));
    }
    if (t < 16) {
        uint32_t dst = CvA + slot * 256 + t * 16;
        asm volatile("cp.async.ca.shared.global [%0], [%1], 16;"
                     :: "r"(dst), "l"(&g_Cvec[comp][t * 4]));
    }
}

// acc(16x64) = -c + Xwarp(16x64) * B(64x64)^T, B lower-triangular
__device__ __forceinline__ void gemm_tile(float acc[8][4],
                                          const uint32_t afr[4][4],
                                          uint32_t LbB, const float2 ci[8],
                                          int lr, int lc) {
#pragma unroll
    for (int n8 = 0; n8 < 8; n8++) {
        acc[n8][0] = -ci[n8].x; acc[n8][1] = -ci[n8].y;
        acc[n8][2] = -ci[n8].x; acc[n8][3] = -ci[n8].y;
    }
#pragma unroll
    for (int ks = 0; ks < 4; ks++) {
        uint32_t b[8][2];
#pragma unroll
        for (int ng = 0; ng < 4; ng++) {
            if (ks >= 2 && ng < 2) continue;   // triangular: rows<32 need K<32
            uint32_t r[4];
            ldmx4(r, LbB + (ng * 16 + lr) * ROWB + ks * 32 + lc);
            b[2 * ng][0] = r[0]; b[2 * ng][1] = r[2];
            b[2 * ng + 1][0] = r[1]; b[2 * ng + 1][1] = r[3];
        }
#pragma unroll
        for (int n8 = 0; n8 < 8; n8++) {
            if (ks >= 2 && n8 < 4) continue;
            mma16816(acc[n8], afr[ks], b[n8][0], b[n8][1]);
        }
    }
}

__global__ __launch_bounds__(128, 4) void main_kernel(const float* __restrict__ x,
                                                      float* __restrict__ out) {
    extern __shared__ char smem[];
    __nv_bfloat16* Xs = (__nv_bfloat16*)smem;
    float* cArea = (float*)(smem + CV_OFF);
    double* dsm = (double*)(smem + DSM_OFF);

    const int t = threadIdx.x;
    const int w = t >> 5, l = t & 31;
    const int m0w = w * 16;
    const int b0 = blockIdx.x * 64;
    uint32_t sbase = (uint32_t)__cvta_generic_to_shared(smem);
    uint32_t LbA = sbase + LB_OFF;
    uint32_t CvA = sbase + CV_OFF;
    uint32_t XsW = sbase + m0w * ROWB;
    const int lr = (l & 15);
    const int lc = (l >> 4) * 16;
    const bool own = ((l & 3) == 0);

    // ---- load X tile (64x64 f32) -> bf16 smem ----
    {
        const float4* X4 = (const float4*)(x + (size_t)b0 * 64);
#pragma unroll
        for (int q = 0; q < 8; q++) {
            int f = t + q * 128;            // 0..1023
            int row = f >> 4, cq = f & 15;
            float4 vv = X4[f];
            __nv_bfloat162 pp0 = __float22bfloat162_rn(make_float2(vv.x, vv.y));
            __nv_bfloat162 pp1 = __float22bfloat162_rn(make_float2(vv.z, vv.w));
            uint2 pk;
            pk.x = *reinterpret_cast<uint32_t*>(&pp0);
            pk.y = *reinterpret_cast<uint32_t*>(&pp1);
            *reinterpret_cast<uint2*>(&Xs[row * 72 + cq * 4]) = pk;
        }
    }

    // ---- prologue: stage comps 0..3 into slots 0..3 ----
#pragma unroll
    for (int k = 0; k < NSLOT; k++) {
        cp_slot(LbA, CvA, k, k, t);
        asm volatile("cp.async.commit_group;");
    }

    __syncthreads();   // Xs visible

    // ---- hoist A fragments (16 rows per warp) ----
    uint32_t afr[4][4];
#pragma unroll
    for (int ks = 0; ks < 4; ks++)
        ldmx4(afr[ks], XsW + lr * ROWB + ks * 32 + lc);

    float acc[8][4];
    float runm[2], runs[2];
#pragma unroll
    for (int i = 0; i < 2; i++) { runm[i] = -INFINITY; runs[i] = 0.0f; }

    // groups of 2 comps: 2 barriers / 2 comps
    for (int g = 0; g < KC; g += 2) {
        asm volatile("cp.async.wait_group 2;");   // comps g, g+1 resident
        __syncthreads();

#pragma unroll
        for (int kk = 0; kk < 2; kk++) {
            const int k = g + kk;
            const int slot = k & (NSLOT - 1);

            float2 ci[8];
            const float2* cv = (const float2*)(cArea + slot * 64);
#pragma unroll
            for (int n8 = 0; n8 < 8; n8++)
                ci[n8] = cv[n8 * 4 + (l & 3)];

            gemm_tile(acc, afr, LbA + slot * LB_BYTES, ci, lr, lc);

            float p[2];
            {
                float s0 = 0.0f, s1 = 0.0f;
#pragma unroll
                for (int n8 = 0; n8 < 8; n8++) {
                    s0 = fmaf(acc[n8][0], acc[n8][0], s0);
                    s0 = fmaf(acc[n8][1], acc[n8][1], s0);
                    s1 = fmaf(acc[n8][2], acc[n8][2], s1);
                    s1 = fmaf(acc[n8][3], acc[n8][3], s1);
                }
                p[0] = s0; p[1] = s1;
            }
#pragma unroll
            for (int off = 1; off <= 2; off <<= 1) {
                p[0] += __shfl_xor_sync(0xffffffffu, p[0], off);
                p[1] += __shfl_xor_sync(0xffffffffu, p[1], off);
            }

            if (own) {
                float c2 = g_const2[k];
#pragma unroll
                for (int i = 0; i < 2; i++) {
                    float s = fmaf(-0.5f, p[i], c2);
                    float nm = fmaxf(runm[i], s);
                    runs[i] = runs[i] * __expf(runm[i] - nm) + __expf(s - nm);
                    runm[i] = nm;
                }
            }
        }

        __syncthreads();   // all warps done reading slots g, g+1
#pragma unroll
        for (int kk = 0; kk < 2; kk++) {
            const int kp = g + NSLOT + kk;
            if (kp < KC) cp_slot(LbA, CvA, kp & (NSLOT - 1), kp, t);
            asm volatile("cp.async.commit_group;");
        }
    }

    // ---- per-CTA deterministic reduction ----
    double lps = 0.0;
    if (own)
        lps = (double)(runm[0] + logf(runs[0])) + (double)(runm[1] + logf(runs[1]));
#pragma unroll
    for (int off = 16; off > 0; off >>= 1)
        lps += __shfl_xor_sync(0xffffffffu, lps, off);
    if (l == 0) dsm[w] = lps;
    __syncthreads();
    if (t == 0)
        g_partial[blockIdx.x] = dsm[0] + dsm[1] + dsm[2] + dsm[3];

    // ---- last-block final reduction (512 partials) ----
    __shared__ bool isLast;
    __threadfence();
    if (t == 0) isLast = (atomicAdd(&g_cnt, 1u) == 511u);
    __syncthreads();
    if (isLast) {
        __threadfence();
        const volatile double* gp = (const volatile double*)g_partial;
        __shared__ double dd[128];
        dd[t] = (gp[t] + gp[t + 128]) + (gp[t + 256] + gp[t + 384]);
        __syncthreads();
        for (int s = 64; s > 0; s >>= 1) {
            if (t < s) dd[t] += dd[t + s];
            __syncthreads();
        }
        if (t == 0) out[0] = (float)(-dd[0] / (double)BTOT);
    }
}

// ============================================================
extern "C" void kernel_launch(void* const* d_in, const int* in_sizes, int n_in,
                              void* d_out, int out_size) {
    const float* x           = (const float*)d_in[0];
    const float* means_raw   = (const float*)d_in[1];
    const float* scale_raw   = (const float*)d_in[2];
    const float* weights_raw = (const float*)d_in[3];
    float* out = (float*)d_out;

    cudaFuncSetAttribute(main_kernel, cudaFuncAttributeMaxDynamicSharedMemorySize,
                         SMEM_TOTAL);

    prep_kernel<<<64, 256>>>(means_raw, scale_raw, weights_raw);
    main_kernel<<<512, 128, SMEM_TOTAL>>>(x, out);
}

// round 11
// speedup vs baseline: 1.0469x; 1.0469x over previous
#include <cuda_runtime.h>
#include <cuda_bf16.h>
#include <cstdint>
#include <math.h>

#define BTOT 32768
#define KC 64
#define DD 64
#define LOG_2PI 1.8378770664093453f

// ---- persistent scratch ----
__device__ __nv_bfloat16 g_LinvBF[KC][DD * DD];  // [k][i*64+j] (lower-tri, upper=0)
__device__ float    g_Cvec[KC][DD];              // c_k[i] = (Linv mu)[i], fp32
__device__ float    g_const2[KC];  // logw - hld - 0.5*D*log2pi
__device__ float    g_rowm[2][BTOT];             // per-half per-row running max
__device__ float    g_rows[2][BTOT];             // per-half per-row running sum
__device__ double   g_partial[256];
__device__ unsigned g_cntp[256];                 // per-tile pair counters
__device__ unsigned g_cnt;

// ============================================================
// Kernel A: preprocess, 64 blocks x 256 threads (8 warps).
// Warp-register column solver.
// ============================================================
__global__ __launch_bounds__(256) void prep_kernel(const float* __restrict__ means_raw,
                                                   const float* __restrict__ scale_raw,
                                                   const float* __restrict__ weights_raw) {
    const int k = blockIdx.x;
    const int t = threadIdx.x;
    const int w = t >> 5, l = t & 31;
    __shared__ float Lp[DD][DD + 1];
    __shared__ float R[DD][DD + 1];
    __shared__ float dg[DD];
    __shared__ float aux[DD];
    __shared__ float aux2[DD];
    __shared__ float mv[DD];
    const float g2 = 1.0f / 512.0f;
    const float g1 = 1.0f / 64.0f;

    if (k == 0) {                      // reset counters each call
        if (t == 0) g_cnt = 0;
        if (t < 256) g_cntp[t] = 0;
    }

    for (int idx = t; idx < DD * DD; idx += 256) {
        int i = idx >> 6, j = idx & 63;
        float raw = scale_raw[k * DD * DD + idx] * g2;
        Lp[i][j] = (i > j) ? raw : 0.0f;
        if (i == j) dg[i] = raw;
    }
    float v = 0.0f;
    if (t < 64) {
        mv[t] = means_raw[k * DD + t] * g1;
        v = weights_raw[t] * 0.125f;
        aux[t] = v;
    }
    __syncthreads();

    for (int s = 32; s > 0; s >>= 1) {
        if (t < s) aux[t] = fmaxf(aux[t], aux[t + s]);
        __syncthreads();
    }
    float m = aux[0];
    __syncthreads();
    if (t < 64) { aux2[t] = expf(v - m); aux[t] = dg[t]; }
    __syncthreads();
    for (int s = 32; s > 0; s >>= 1) {
        if (t < s) { aux2[t] += aux2[t + s]; aux[t] += aux[t + s]; }
        __syncthreads();
    }
    float lse = m + logf(aux2[0]);
    float hld = aux[0];

    // register column solver: lane l = rows l, l+32
    float rd0 = __expf(-dg[l]);
    float rd1 = __expf(-dg[l + 32]);
    float p0[8], p1[8], y0[8], y1[8];
#pragma unroll
    for (int j = 0; j < 8; j++) { p0[j] = p1[j] = y0[j] = y1[j] = 0.0f; }
    const int cbase = w * 8;

    for (int i = 0; i < DD; i++) {
        float Llo = Lp[l][i];
        float Lhi = Lp[l + 32][i];
        const int own = i & 31;
        const int half = i >> 5;
        float rdo = half ? rd1 : rd0;
#pragma unroll
        for (int j = 0; j < 8; j++) {
            const int c = cbase + j;
            float pown = half ? p1[j] : p0[j];
            float cv = ((i == c) ? 1.0f : 0.0f) - pown;
            cv *= rdo;
            float yb = __shfl_sync(0xffffffffu, cv, own);
            yb = (i >= c) ? yb : 0.0f;
            if (l == own) { if (half) y1[j] = yb; else y0[j] = yb; }
            p0[j] = fmaf(Llo, yb, p0[j]);
            p1[j] = fmaf(Lhi, yb, p1[j]);
        }
    }

#pragma unroll
    for (int j = 0; j < 8; j++) {
        R[l][cbase + j]      = y0[j];
        R[l + 32][cbase + j] = y1[j];
    }
    __syncthreads();

    if (t < 64) {
        float c = 0.0f;
        for (int j = 0; j <= t; j++) c += R[t][j] * mv[j];
        g_Cvec[k][t] = c;
    }

    for (int idx = t; idx < DD * DD; idx += 256) {
        int i = idx >> 6, j = idx & 63;
        g_LinvBF[k][idx] = __float2bfloat16(R[i][j]);
    }

    if (t == 0) {
        float vk = weights_raw[k] * 0.125f;
        g_const2[k] = (vk - lse) - hld - 0.5f * 64.0f * LOG_2PI;
    }
}

// ============================================================
// Main kernel: 512 CTAs x 128 thr. CTA = (row tile 128) x (K half
// of 32 comps). Warp M32xN64, N processed in 2 sequential halves
// (acc 32 regs -> 4 CTAs/SM, single wave, ~16 warps/SM).
// B-LDSM total identical to R9. Cross-CTA logsumexp merge.
// ============================================================
#define ROWB 144
#define XS_BYTES (128 * ROWB)           // 18432
#define LB_OFF   XS_BYTES
#define LB_BYTES (64 * ROWB)            // 9216 per slot
#define NSLOT 4
#define CV_OFF   (LB_OFF + NSLOT * LB_BYTES)    // 55296
#define CV_BYTES (NSLOT * 256)                  // 1024
#define DSM_OFF  (CV_OFF + CV_BYTES)            // 56320
#define SMEM_TOTAL (DSM_OFF + 128 * 8)          // 57344

__device__ __forceinline__ void ldmx4(uint32_t a[4], uint32_t addr) {
    asm volatile("ldmatrix.sync.aligned.m8n8.x4.shared.b16 {%0,%1,%2,%3}, [%4];"
                 : "=r"(a[0]), "=r"(a[1]), "=r"(a[2]), "=r"(a[3]) : "r"(addr));
}
__device__ __forceinline__ void mma16816(float d[4], const uint32_t a[4],
                                         uint32_t b0, uint32_t b1) {
    asm volatile(
        "mma.sync.aligned.m16n8k16.row.col.f32.bf16.bf16.f32 "
        "{%0,%1,%2,%3}, {%4,%5,%6,%7}, {%8,%9}, {%0,%1,%2,%3};"
        : "+f"(d[0]), "+f"(d[1]), "+f"(d[2]), "+f"(d[3])
        : "r"(a[0]), "r"(a[1]), "r"(a[2]), "r"(a[3]), "r"(b0), "r"(b1));
}
__device__ __forceinline__ void cp_slot(uint32_t LbA, uint32_t CvA, int slot,
                                        int comp, int t) {
    uint32_t dstB = LbA + slot * LB_BYTES;
    const __nv_bfloat16* src = g_LinvBF[comp];
#pragma unroll
    for (int q = 0; q < 4; q++) {
        int f = t + q * 128;
        uint32_t dst = dstB + (f >> 3) * ROWB + (f & 7) * 16;
        asm volatile("cp.async.ca.shared.global [%0], [%1], 16;"
                     :: "r"(dst), "l"(src + f * 8));
    }
    if (t < 16) {
        uint32_t dst = CvA + slot * 256 + t * 16;
        asm volatile("cp.async.ca.shared.global [%0], [%1], 16;"
                     :: "r"(dst), "l"(&g_Cvec[comp][t * 4]));
    }
}

// acc(32x32) = -c + X(32x64) * Brows[hi*32..+32]^T.
// hi=0: output dims 0..31, triangular -> only ks 0..1.
// hi=1: output dims 32..63, all ks.
template <int HI>
__device__ __forceinline__ void gemm_half(float acc[2][4][4],
                                          const uint32_t afr[4][2][4],
                                          uint32_t LbB, const float2 ci[4],
                                          int lr, int lc) {
#pragma unroll
    for (int n8 = 0; n8 < 4; n8++) {
        acc[0][n8][0] = -ci[n8].x; acc[0][n8][1] = -ci[n8].y;
        acc[0][n8][2] = -ci[n8].x; acc[0][n8][3] = -ci[n8].y;
        acc[1][n8][0] = -ci[n8].x; acc[1][n8][1] = -ci[n8].y;
        acc[1][n8][2] = -ci[n8].x; acc[1][n8][3] = -ci[n8].y;
    }
    const int NKS = HI ? 4 : 2;
#pragma unroll
    for (int ks = 0; ks < NKS; ks++) {
        uint32_t b[4][2];
#pragma unroll
        for (int ngl = 0; ngl < 2; ngl++) {
            uint32_t r[4];
            ldmx4(r, LbB + ((HI * 2 + ngl) * 16 + lr) * ROWB + ks * 32 + lc);
            b[2 * ngl][0] = r[0]; b[2 * ngl][1] = r[2];
            b[2 * ngl + 1][0] = r[1]; b[2 * ngl + 1][1] = r[3];
        }
#pragma unroll
        for (int ma = 0; ma < 2; ma++)
#pragma unroll
            for (int n8 = 0; n8 < 4; n8++)
                mma16816(acc[ma][n8], afr[ks][ma], b[n8][0], b[n8][1]);
    }
}

__device__ __forceinline__ void addsq(float p[4], const float acc[2][4][4]) {
#pragma unroll
    for (int ma = 0; ma < 2; ma++) {
        float s0 = p[ma * 2], s1 = p[ma * 2 + 1];
#pragma unroll
        for (int n8 = 0; n8 < 4; n8++) {
            s0 = fmaf(acc[ma][n8][0], acc[ma][n8][0], s0);
            s0 = fmaf(acc[ma][n8][1], acc[ma][n8][1], s0);
            s1 = fmaf(acc[ma][n8][2], acc[ma][n8][2], s1);
            s1 = fmaf(acc[ma][n8][3], acc[ma][n8][3], s1);
        }
        p[ma * 2] = s0; p[ma * 2 + 1] = s1;
    }
}

__global__ __launch_bounds__(128, 4) void main_kernel(const float* __restrict__ x,
                                                      float* __restrict__ out) {
    extern __shared__ char smem[];
    __nv_bfloat16* Xs = (__nv_bfloat16*)smem;
    float* cArea = (float*)(smem + CV_OFF);
    double* dsm = (double*)(smem + DSM_OFF);

    const int t = threadIdx.x;
    const int w = t >> 5, l = t & 31;
    const int tile = blockIdx.x >> 1;
    const int half = blockIdx.x & 1;
    const int kbase = half * 32;
    const int m0w = w * 32;
    const int b0 = tile * 128;
    uint32_t sbase = (uint32_t)__cvta_generic_to_shared(smem);
    uint32_t LbA = sbase + LB_OFF;
    uint32_t CvA = sbase + CV_OFF;
    uint32_t XsW = sbase + m0w * ROWB;
    const int lr = (l & 15);
    const int lc = (l >> 4) * 16;
    const bool own = ((l & 3) == 0);

    // ---- load X tile (128x64 f32) -> bf16 smem ----
    {
        const float4* X4 = (const float4*)(x + (size_t)b0 * 64);
#pragma unroll
        for (int q = 0; q < 16; q++) {
            int f = t + q * 128;
            int row = f >> 4, cq = f & 15;
            float4 vv = X4[f];
            __nv_bfloat162 pp0 = __float22bfloat162_rn(make_float2(vv.x, vv.y));
            __nv_bfloat162 pp1 = __float22bfloat162_rn(make_float2(vv.z, vv.w));
            uint2 pk;
            pk.x = *reinterpret_cast<uint32_t*>(&pp0);
            pk.y = *reinterpret_cast<uint32_t*>(&pp1);
            *reinterpret_cast<uint2*>(&Xs[row * 72 + cq * 4]) = pk;
        }
    }

    // ---- prologue: stage this half's comps 0..3 ----
#pragma unroll
    for (int k = 0; k < NSLOT; k++) {
        cp_slot(LbA, CvA, k, kbase + k, t);
        asm volatile("cp.async.commit_group;");
    }

    __syncthreads();   // Xs visible

    uint32_t afr[4][2][4];
#pragma unroll
    for (int ks = 0; ks < 4; ks++)
#pragma unroll
        for (int ma = 0; ma < 2; ma++)
            ldmx4(afr[ks][ma], XsW + (ma * 16 + lr) * ROWB + ks * 32 + lc);

    float acc[2][4][4];
    float runm[4], runs[4];
#pragma unroll
    for (int i = 0; i < 4; i++) { runm[i] = -INFINITY; runs[i] = 0.0f; }

    for (int g = 0; g < 32; g += 2) {
        asm volatile("cp.async.wait_group 2;");
        __syncthreads();

#pragma unroll
        for (int kk = 0; kk < 2; kk++) {
            const int kl = g + kk;
            const int k = kbase + kl;
            const int slot = kl & (NSLOT - 1);
            const float2* cv = (const float2*)(cArea + slot * 64);

            float p[4] = {0.0f, 0.0f, 0.0f, 0.0f};
            {
                float2 ci[4];
#pragma unroll
                for (int n8 = 0; n8 < 4; n8++) ci[n8] = cv[n8 * 4 + (l & 3)];
                gemm_half<0>(acc, afr, LbA + slot * LB_BYTES, ci, lr, lc);
                addsq(p, acc);
            }
            {
                float2 ci[4];
#pragma unroll
                for (int n8 = 0; n8 < 4; n8++) ci[n8] = cv[16 + n8 * 4 + (l & 3)];
                gemm_half<1>(acc, afr, LbA + slot * LB_BYTES, ci, lr, lc);
                addsq(p, acc);
            }
#pragma unroll
            for (int off = 1; off <= 2; off <<= 1)
#pragma unroll
                for (int i = 0; i < 4; i++)
                    p[i] += __shfl_xor_sync(0xffffffffu, p[i], off);

            if (own) {
                float c2 = g_const2[k];
#pragma unroll
                for (int i = 0; i < 4; i++) {
                    float s = fmaf(-0.5f, p[i], c2);
                    float nm = fmaxf(runm[i], s);
                    runs[i] = runs[i] * __expf(runm[i] - nm) + __expf(s - nm);
                    runm[i] = nm;
                }
            }
        }

        __syncthreads();
#pragma unroll
        for (int kk = 0; kk < 2; kk++) {
            const int kpl = g + NSLOT + kk;
            if (kpl < 32) cp_slot(LbA, CvA, kpl & (NSLOT - 1), kbase + kpl, t);
            asm volatile("cp.async.commit_group;");
        }
    }

    // ---- write per-row (max,sum) for this half ----
    if (own) {
#pragma unroll
        for (int i = 0; i < 4; i++) {
            int r = m0w + (i >> 1) * 16 + (i & 1) * 8 + (l >> 2);
            g_rowm[half][b0 + r] = runm[i];
            g_rows[half][b0 + r] = runs[i];
        }
    }

    // ---- pair merge: second CTA of the pair merges 128 rows ----
    __shared__ bool doMerge;
    __threadfence();
    if (t == 0) doMerge = (atomicAdd(&g_cntp[tile], 1u) == 1u);
    __syncthreads();
    if (!doMerge) return;

    __threadfence();
    {
        const volatile float* vm0 = g_rowm[0];
        const volatile float* vs0 = g_rows[0];
        const volatile float* vm1 = g_rowm[1];
        const volatile float* vs1 = g_rows[1];
        int r = b0 + t;
        float m0 = vm0[r], s0 = vs0[r], m1 = vm1[r], s1 = vs1[r];
        float M = fmaxf(m0, m1);
        float tot = s0 * __expf(m0 - M) + s1 * __expf(m1 - M);
        dsm[t] = (double)(M + logf(tot));
    }
    __syncthreads();
    for (int s = 64; s > 0; s >>= 1) {
        if (t < s) dsm[t] += dsm[t + s];
        __syncthreads();
    }
    if (t == 0) g_partial[tile] = dsm[0];

    // ---- last tile does final 256-way fixed-order reduction ----
    __shared__ bool isLast;
    __threadfence();
    if (t == 0) isLast = (atomicAdd(&g_cnt, 1u) == 255u);
    __syncthreads();
    if (isLast) {
        __threadfence();
        const volatile double* gp = (const volatile double*)g_partial;
        dsm[t] = gp[t] + gp[t + 128];
        __syncthreads();
        for (int s = 64; s > 0; s >>= 1) {
            if (t < s) dsm[t] += dsm[t + s];
            __syncthreads();
        }
        if (t == 0) out[0] = (float)(-dsm[0] / (double)BTOT);
    }
}

// ============================================================
extern "C" void kernel_launch(void* const* d_in, const int* in_sizes, int n_in,
                              void* d_out, int out_size) {
    const float* x           = (const float*)d_in[0];
    const float* means_raw   = (const float*)d_in[1];
    const float* scale_raw   = (const float*)d_in[2];
    const float* weights_raw = (const float*)d_in[3];
    float* out = (float*)d_out;

    cudaFuncSetAttribute(main_kernel, cudaFuncAttributeMaxDynamicSharedMemorySize,
                         SMEM_TOTAL);

    prep_kernel<<<64, 256>>>(means_raw, scale_raw, weights_raw);
    main_kernel<<<512, 128, SMEM_TOTAL>>>(x, out);
}

// round 13
// speedup vs baseline: 1.2560x; 1.1997x over previous
#include <cuda_runtime.h>
#include <cuda_bf16.h>
#include <cstdint>
#include <math.h>

#define BTOT 32768
#define KC 64
#define DD 64
#define LOG_2PI 1.8378770664093453f

// ---- persistent scratch ----
__device__ __nv_bfloat16 g_LinvBF[KC][DD * DD];  // [k][i*64+j] (lower-tri, upper=0)
__device__ float    g_Cvec[KC][DD];              // c_k[i] = (Linv mu)[i], fp32
__device__ float    g_const2[KC];  // logw - hld - 0.5*D*log2pi
__device__ double   g_partial[256];
__device__ unsigned g_cnt;

// ============================================================
// Kernel A: preprocess (unchanged from R9/R11, minus g_cntp)
// ============================================================
__global__ __launch_bounds__(256) void prep_kernel(const float* __restrict__ means_raw,
                                                   const float* __restrict__ scale_raw,
                                                   const float* __restrict__ weights_raw) {
    const int k = blockIdx.x;
    const int t = threadIdx.x;
    const int w = t >> 5, l = t & 31;
    __shared__ float Lp[DD][DD + 1];
    __shared__ float R[DD][DD + 1];
    __shared__ float dg[DD];
    __shared__ float aux[DD];
    __shared__ float aux2[DD];
    __shared__ float mv[DD];
    const float g2 = 1.0f / 512.0f;
    const float g1 = 1.0f / 64.0f;

    if (k == 0 && t == 0) g_cnt = 0;

    for (int idx = t; idx < DD * DD; idx += 256) {
        int i = idx >> 6, j = idx & 63;
        float raw = scale_raw[k * DD * DD + idx] * g2;
        Lp[i][j] = (i > j) ? raw : 0.0f;
        if (i == j) dg[i] = raw;
    }
    float v = 0.0f;
    if (t < 64) {
        mv[t] = means_raw[k * DD + t] * g1;
        v = weights_raw[t] * 0.125f;
        aux[t] = v;
    }
    __syncthreads();

    for (int s = 32; s > 0; s >>= 1) {
        if (t < s) aux[t] = fmaxf(aux[t], aux[t + s]);
        __syncthreads();
    }
    float m = aux[0];
    __syncthreads();
    if (t < 64) { aux2[t] = expf(v - m); aux[t] = dg[t]; }
    __syncthreads();
    for (int s = 32; s > 0; s >>= 1) {
        if (t < s) { aux2[t] += aux2[t + s]; aux[t] += aux[t + s]; }
        __syncthreads();
    }
    float lse = m + logf(aux2[0]);
    float hld = aux[0];

    float rd0 = __expf(-dg[l]);
    float rd1 = __expf(-dg[l + 32]);
    float p0[8], p1[8], y0[8], y1[8];
#pragma unroll
    for (int j = 0; j < 8; j++) { p0[j] = p1[j] = y0[j] = y1[j] = 0.0f; }
    const int cbase = w * 8;

    for (int i = 0; i < DD; i++) {
        float Llo = Lp[l][i];
        float Lhi = Lp[l + 32][i];
        const int own = i & 31;
        const int half = i >> 5;
        float rdo = half ? rd1 : rd0;
#pragma unroll
        for (int j = 0; j < 8; j++) {
            const int c = cbase + j;
            float pown = half ? p1[j] : p0[j];
            float cv = ((i == c) ? 1.0f : 0.0f) - pown;
            cv *= rdo;
            float yb = __shfl_sync(0xffffffffu, cv, own);
            yb = (i >= c) ? yb : 0.0f;
            if (l == own) { if (half) y1[j] = yb; else y0[j] = yb; }
            p0[j] = fmaf(Llo, yb, p0[j]);
            p1[j] = fmaf(Lhi, yb, p1[j]);
        }
    }

#pragma unroll
    for (int j = 0; j < 8; j++) {
        R[l][cbase + j]      = y0[j];
        R[l + 32][cbase + j] = y1[j];
    }
    __syncthreads();

    if (t < 64) {
        float c = 0.0f;
        for (int j = 0; j <= t; j++) c += R[t][j] * mv[j];
        g_Cvec[k][t] = c;
    }

    for (int idx = t; idx < DD * DD; idx += 256) {
        int i = idx >> 6, j = idx & 63;
        g_LinvBF[k][idx] = __float2bfloat16(R[i][j]);
    }

    if (t == 0) {
        float vk = weights_raw[k] * 0.125f;
        g_const2[k] = (vk - lse) - hld - 0.5f * 64.0f * LOG_2PI;
    }
}

// ============================================================
// Main: warp-specialized. 256 CTAs x 256 thr.
// Warps 0-3: pure MMA producers (M32xN64 each, 128-row tile).
// Warps 4-7: cp.async staging + logsumexp consumers (1 iter behind).
// 8-slot B ring, 1 __syncthreads per 2 comps, P parity buffer.
// ============================================================
#define ROWB 144
#define XS_BYTES (128 * ROWB)                   // 18432
#define LB_OFF   XS_BYTES
#define LB_BYTES (64 * ROWB)                    // 9216
#define NSLOT 8
#define CV_OFF   (LB_OFF + NSLOT * LB_BYTES)    // 92160
#define C2_OFF   (CV_OFF + NSLOT * 256)         // 94208
#define P_OFF    (C2_OFF + 256)                 // 94464
#define P_BYTES  (2 * 2 * 4 * 32 * 4 * 4)       // par x kk x warp x row x colgrp = 8192
#define DSM_OFF  (P_OFF + P_BYTES)              // 102656
#define SMEM_TOTAL (DSM_OFF + 128 * 8)          // 103680

__device__ __forceinline__ void ldmx4(uint32_t a[4], uint32_t addr) {
    asm volatile("ldmatrix.sync.aligned.m8n8.x4.shared.b16 {%0,%1,%2,%3}, [%4];"
                 : "=r"(a[0]), "=r"(a[1]), "=r"(a[2]), "=r"(a[3]) : "r"(addr));
}
__device__ __forceinline__ void mma16816(float d[4], const uint32_t a[4],
                                         uint32_t b0, uint32_t b1) {
    asm volatile(
        "mma.sync.aligned.m16n8k16.row.col.f32.bf16.bf16.f32 "
        "{%0,%1,%2,%3}, {%4,%5,%6,%7}, {%8,%9}, {%0,%1,%2,%3};"
        : "+f"(d[0]), "+f"(d[1]), "+f"(d[2]), "+f"(d[3])
        : "r"(a[0]), "r"(a[1]), "r"(a[2]), "r"(a[3]), "r"(b0), "r"(b1));
}
// epi threads (te = 0..127) stage Linv[comp] + c vector into slot
__device__ __forceinline__ void cp_slot(uint32_t LbA, uint32_t CvA, int slot,
                                        int comp, int te) {
    uint32_t dstB = LbA + slot * LB_BYTES;
    const __nv_bfloat16* src = g_LinvBF[comp];
#pragma unroll
    for (int q = 0; q < 4; q++) {
        int f = te + q * 128;
        uint32_t dst = dstB + (f >> 3) * ROWB + (f & 7) * 16;
        asm volatile("cp.async.ca.shared.global [%0], [%1], 16;"
                     :: "r"(dst), "l"(src + f * 8));
    }
    if (te < 16) {
        uint32_t dst = CvA + slot * 256 + te * 16;
        asm volatile("cp.async.ca.shared.global [%0], [%1], 16;"
                     :: "r"(dst), "l"(&g_Cvec[comp][te * 4]));
    }
}

// acc(32x64) = -c + X(32x64)*B^T, B lower-triangular (skip ks>=2 for cols<32)
__device__ __forceinline__ void gemm_tile(float acc[2][8][4],
                                          const uint32_t afr[4][2][4],
                                          uint32_t LbB, const float2 ci[8],
                                          int lr, int lc) {
#pragma unroll
    for (int n8 = 0; n8 < 8; n8++) {
        acc[0][n8][0] = -ci[n8].x; acc[0][n8][1] = -ci[n8].y;
        acc[0][n8][2] = -ci[n8].x; acc[0][n8][3] = -ci[n8].y;
        acc[1][n8][0] = -ci[n8].x; acc[1][n8][1] = -ci[n8].y;
        acc[1][n8][2] = -ci[n8].x; acc[1][n8][3] = -ci[n8].y;
    }
#pragma unroll
    for (int ks = 0; ks < 4; ks++) {
        uint32_t b[8][2];
#pragma unroll
        for (int ng = 0; ng < 4; ng++) {
            if (ks >= 2 && ng < 2) continue;
            uint32_t r[4];
            ldmx4(r, LbB + (ng * 16 + lr) * ROWB + ks * 32 + lc);
            b[2 * ng][0] = r[0]; b[2 * ng][1] = r[2];
            b[2 * ng + 1][0] = r[1]; b[2 * ng + 1][1] = r[3];
        }
#pragma unroll
        for (int ma = 0; ma < 2; ma++)
#pragma unroll
            for (int n8 = 0; n8 < 8; n8++) {
                if (ks >= 2 && n8 < 4) continue;
                mma16816(acc[ma][n8], afr[ks][ma], b[n8][0], b[n8][1]);
            }
    }
}

__global__ __launch_bounds__(256, 2) void main_kernel(const float* __restrict__ x,
                                                      float* __restrict__ out) {
    extern __shared__ char smem[];
    __nv_bfloat16* Xs = (__nv_bfloat16*)smem;
    float* c2S = (float*)(smem + C2_OFF);
    float* P   = (float*)(smem + P_OFF);
    double* dsm = (double*)(smem + DSM_OFF);

    const int t = threadIdx.x;
    const int w = t >> 5, l = t & 31;
    const bool isMMA = (w < 4);
    const int e = w - 4;                 // epi warp index 0..3
    const int te = t - 128;              // epi thread index 0..127
    const int b0 = blockIdx.x * 128;
    uint32_t sbase = (uint32_t)__cvta_generic_to_shared(smem);
    uint32_t LbA = sbase + LB_OFF;
    uint32_t CvA = sbase + CV_OFF;
    const int lr = (l & 15);
    const int lc = (l >> 4) * 16;

    // ---- X tile (128x64 f32) -> bf16 smem, all 256 threads ----
    {
        const float4* X4 = (const float4*)(x + (size_t)b0 * 64);
#pragma unroll
        for (int q = 0; q < 8; q++) {
            int f = t + q * 256;
            int row = f >> 4, cq = f & 15;
            float4 vv = X4[f];
            __nv_bfloat162 pp0 = __float22bfloat162_rn(make_float2(vv.x, vv.y));
            __nv_bfloat162 pp1 = __float22bfloat162_rn(make_float2(vv.z, vv.w));
            uint2 pk;
            pk.x = *reinterpret_cast<uint32_t*>(&pp0);
            pk.y = *reinterpret_cast<uint32_t*>(&pp1);
            *reinterpret_cast<uint2*>(&Xs[row * 72 + cq * 4]) = pk;
        }
    }

    // ---- prologue staging (epi threads): const2 + comps 0..5, 3 groups ----
    if (!isMMA) {
        if (te < 16) {
            uint32_t dst = sbase + C2_OFF + te * 16;
            asm volatile("cp.async.ca.shared.global [%0], [%1], 16;"
                         :: "r"(dst), "l"(&g_const2[te * 4]));
        }
        cp_slot(LbA, CvA, 0, 0, te);
        cp_slot(LbA, CvA, 1, 1, te);
        asm volatile("cp.async.commit_group;");
        cp_slot(LbA, CvA, 2, 2, te);
        cp_slot(LbA, CvA, 3, 3, te);
        asm volatile("cp.async.commit_group;");
        cp_slot(LbA, CvA, 4, 4, te);
        cp_slot(LbA, CvA, 5, 5, te);
        asm volatile("cp.async.commit_group;");
    }
    __syncthreads();   // Xs visible to MMA warps

    uint32_t afr[4][2][4];
    if (isMMA) {
        uint32_t XsW = sbase + w * 32 * ROWB;
#pragma unroll
        for (int ks = 0; ks < 4; ks++)
#pragma unroll
            for (int ma = 0; ma < 2; ma++)
                ldmx4(afr[ks][ma], XsW + (ma * 16 + lr) * ROWB + ks * 32 + lc);
    }

    float runm = -INFINITY, runs = 0.0f;   // epi: per-lane row state

    for (int g = 0; g < KC; g += 2) {
        const int par = (g >> 1) & 1;
        if (!isMMA) asm volatile("cp.async.wait_group 2;");
        __syncthreads();   // slots g,g+1 ready; P[par^1] (comps g-2,g-1) complete

        if (isMMA) {
            float acc[2][8][4];
#pragma unroll
            for (int kk = 0; kk < 2; kk++) {
                const int k = g + kk;
                const int slot = k & (NSLOT - 1);
                float2 ci[8];
                const float2* cv = (const float2*)(smem + CV_OFF + slot * 256);
#pragma unroll
                for (int n8 = 0; n8 < 8; n8++)
                    ci[n8] = cv[n8 * 4 + (l & 3)];

                gemm_tile(acc, afr, LbA + slot * LB_BYTES, ci, lr, lc);

                // raw partial sums of squares: p[i] = this lane's 16-col partial
                float p[4];
#pragma unroll
                for (int ma = 0; ma < 2; ma++) {
                    float s0 = 0.0f, s1 = 0.0f;
#pragma unroll
                    for (int n8 = 0; n8 < 8; n8++) {
                        s0 = fmaf(acc[ma][n8][0], acc[ma][n8][0], s0);
                        s0 = fmaf(acc[ma][n8][1], acc[ma][n8][1], s0);
                        s1 = fmaf(acc[ma][n8][2], acc[ma][n8][2], s1);
                        s1 = fmaf(acc[ma][n8][3], acc[ma][n8][3], s1);
                    }
                    p[ma * 2] = s0; p[ma * 2 + 1] = s1;
                }
                // store raw partials: P[par][kk][w][row_local][colgrp]
                float* Pb = P + ((par * 2 + kk) * 4 + w) * 128;
#pragma unroll
                for (int i = 0; i < 4; i++) {
                    int row = (i >> 1) * 16 + (i & 1) * 8 + (l >> 2);
                    Pb[row * 4 + (l & 3)] = p[i];
                }
            }
        } else {
            // prefetch comps g+6, g+7 into slots freed 2 iterations ago
            const int kp0 = g + 6, kp1 = g + 7;
            if (kp0 < KC) cp_slot(LbA, CvA, kp0 & (NSLOT - 1), kp0, te);
            if (kp1 < KC) cp_slot(LbA, CvA, kp1 & (NSLOT - 1), kp1, te);
            asm volatile("cp.async.commit_group;");

            // logsumexp for comps g-2, g-1 from P[par^1]; lane l <-> row e*32+l
            if (g > 0) {
                const int parp = par ^ 1;
#pragma unroll
                for (int kk = 0; kk < 2; kk++) {
                    const int k = g - 2 + kk;
                    float c2 = c2S[k];
                    const float4* Pb = (const float4*)(P + ((parp * 2 + kk) * 4 + e) * 128);
                    float4 v = Pb[l];
                    float pm = (v.x + v.y) + (v.z + v.w);
                    float s = fmaf(-0.5f, pm, c2);
                    float nm = fmaxf(runm, s);
                    runs = runs * __expf(runm - nm) + __expf(s - nm);
                    runm = nm;
                }
            }
        }
    }

    // ---- drain: comps 62,63 live in P[1] ----
    __syncthreads();
    if (!isMMA) {
#pragma unroll
        for (int kk = 0; kk < 2; kk++) {
            const int k = KC - 2 + kk;
            float c2 = c2S[k];
            const float4* Pb = (const float4*)(P + ((1 * 2 + kk) * 4 + e) * 128);
            float4 v = Pb[l];
            float pm = (v.x + v.y) + (v.z + v.w);
            float s = fmaf(-0.5f, pm, c2);
            float nm = fmaxf(runm, s);
            runs = runs * __expf(runm - nm) + __expf(s - nm);
            runm = nm;
        }
        dsm[e * 32 + l] = (double)(runm + logf(runs));
    }
    __syncthreads();

    // ---- per-CTA fixed-order tree over 128 rows ----
    for (int s = 64; s > 0; s >>= 1) {
        if (t < s) dsm[t] += dsm[t + s];
        __syncthreads();
    }
    if (t == 0) g_partial[blockIdx.x] = dsm[0];

    // ---- last-block final reduction (256 partials) ----
    __shared__ bool isLast;
    __threadfence();
    if (t == 0) isLast = (atomicAdd(&g_cnt, 1u) == 255u);
    __syncthreads();
    if (isLast) {
        __threadfence();
        const volatile double* gp = (const volatile double*)g_partial;
        if (t < 128) dsm[t] = gp[t] + gp[t + 128];
        __syncthreads();
        for (int s = 64; s > 0; s >>= 1) {
            if (t < s) dsm[t] += dsm[t + s];
            __syncthreads();
        }
        if (t == 0) out[0] = (float)(-dsm[0] / (double)BTOT);
    }
}

// ============================================================
extern "C" void kernel_launch(void* const* d_in, const int* in_sizes, int n_in,
                              void* d_out, int out_size) {
    const float* x           = (const float*)d_in[0];
    const float* means_raw   = (const float*)d_in[1];
    const float* scale_raw   = (const float*)d_in[2];
    const float* weights_raw = (const float*)d_in[3];
    float* out = (float*)d_out;

    cudaFuncSetAttribute(main_kernel, cudaFuncAttributeMaxDynamicSharedMemorySize,
                         SMEM_TOTAL);

    prep_kernel<<<64, 256>>>(means_raw, scale_raw, weights_raw);
    main_kernel<<<256, 256, SMEM_TOTAL>>>(x, out);
}